// round 15
// baseline (speedup 1.0000x reference)
#include <cuda_runtime.h>
#include <cuda_fp16.h>
#include <cstdint>

// TopKRouter via mma.sync f16 (hi/lo split, 3-pass): logits = x@W + b ; softmax E=64 ; top-2
// x: (16384, 2048) fp32, W: (2048, 64) fp32, b: (64,)
// out f32: [0..2M) = topk_idx as float (M,2) ; [2M..4M) = topk_vals (M,2)
// R12: A loaded gmem->registers directly in fragment layout (no A smem round trip);
//      B per khalf-pair via cp.async + 64-thread named barriers (pairs decoupled).

#define DK 2048
#define NE 64
#define KS 64
#define MTILE 32
#define NSLAB (DK / KS)         // 32
#define NTHREADS 128
#define SCALE_LO 2048.0f
#define INV_LO   4.8828125e-4f  // 2^-11

#define BUF_BYTES 16384         // Bh(8K) Bl(8K)
#define OFF_BH 0
#define OFF_BL 8192
#define OFF_BIAS (2 * BUF_BYTES)        // 32768
#define SMEM_TOTAL (OFF_BIAS + 512)

#define SWZ(a) ((a) ^ (((a) >> 3) & 0x70))

__device__ uint16_t g_Wh[DK * NE];
__device__ uint16_t g_Wl[DK * NE];

__device__ __forceinline__ uint32_t su32(const void* p) {
    uint32_t a;
    asm("{ .reg .u64 t; cvta.to.shared.u64 t, %1; cvt.u32.u64 %0, t; }" : "=r"(a) : "l"(p));
    return a;
}
__device__ __forceinline__ void cp_async16(uint32_t saddr, const void* g) {
    asm volatile("cp.async.cg.shared.global [%0], [%1], 16;" :: "r"(saddr), "l"(g));
}
#define CP_COMMIT() asm volatile("cp.async.commit_group;" ::: "memory")
#define CP_WAIT0()  asm volatile("cp.async.wait_group 0;" ::: "memory")
#define BAR_PAIR(id) asm volatile("bar.sync %0, 64;" :: "r"(id) : "memory")

__device__ __forceinline__ void split_h(float v, uint16_t& h, uint16_t& l) {
    __half hh = __float2half_rn(v);
    float r = (v - __half2float(hh)) * SCALE_LO;
    __half ll = __float2half_rn(r);
    h = __half_as_ushort(hh);
    l = __half_as_ushort(ll);
}
// split a float2 into packed hi pair (return) and packed lo pair (out-param)
__device__ __forceinline__ uint32_t packsplit(float2 v, uint32_t& lo) {
    uint16_t h0, l0, h1, l1;
    split_h(v.x, h0, l0);
    split_h(v.y, h1, l1);
    lo = (uint32_t)l0 | ((uint32_t)l1 << 16);
    return (uint32_t)h0 | ((uint32_t)h1 << 16);
}

#define LDSM_X4T(r0, r1, r2, r3, a)                                            \
    asm volatile("ldmatrix.sync.aligned.m8n8.x4.trans.shared.b16 {%0,%1,%2,%3}, [%4];" \
                 : "=r"(r0), "=r"(r1), "=r"(r2), "=r"(r3) : "r"(a))

#define MMA16816(d, a0, a1, a2, a3, b0, b1)                                    \
    asm volatile("mma.sync.aligned.m16n8k16.row.col.f32.f16.f16.f32 "          \
                 "{%0,%1,%2,%3}, {%4,%5,%6,%7}, {%8,%9}, {%0,%1,%2,%3};"       \
                 : "+f"((d)[0]), "+f"((d)[1]), "+f"((d)[2]), "+f"((d)[3])      \
                 : "r"(a0), "r"(a1), "r"(a2), "r"(a3), "r"(b0), "r"(b1))

__global__ void wconv_kernel(const float* __restrict__ W) {
    int i = (blockIdx.x * blockDim.x + threadIdx.x) * 4;
    float4 v = *(const float4*)(W + i);
    uint16_t h[4], l[4];
    split_h(v.x, h[0], l[0]); split_h(v.y, h[1], l[1]);
    split_h(v.z, h[2], l[2]); split_h(v.w, h[3], l[3]);
    *(uint2*)(g_Wh + i) = make_uint2((uint32_t)h[0] | ((uint32_t)h[1] << 16),
                                     (uint32_t)h[2] | ((uint32_t)h[3] << 16));
    *(uint2*)(g_Wl + i) = make_uint2((uint32_t)l[0] | ((uint32_t)l[1] << 16),
                                     (uint32_t)l[2] | ((uint32_t)l[3] << 16));
}

// Each khalf pair (64 threads, tp in [0,64)) loads its own 32 B-rows (hi+lo = 8KB)
__device__ __forceinline__ void issue_B_pair(uint32_t sb, int buf, int c,
                                             int khalf, int tp) {
    uint32_t dst = sb + buf * BUF_BYTES;
#pragma unroll
    for (int r = 0; r < 4; r++) {
        int idx = r * 64 + tp;          // 0..255
        int krow = idx >> 3;            // 0..31
        int q = idx & 7;                // 16B chunk within row
        int row = khalf * 32 + krow;
        uint32_t off = SWZ((uint32_t)(row * 128 + q * 16));
        size_t ge = (size_t)(c * KS + row) * NE + q * 8;   // in halves
        cp_async16(dst + OFF_BH + off, (const char*)g_Wh + ge * 2);
        cp_async16(dst + OFF_BL + off, (const char*)g_Wl + ge * 2);
    }
    CP_COMMIT();
}

__global__ __launch_bounds__(NTHREADS)
void router_kernel(const float* __restrict__ x,
                   const float* __restrict__ bias,
                   float* __restrict__ out,
                   int M)
{
    extern __shared__ char smem[];
    const uint32_t sb = su32(smem);
    const int tid = threadIdx.x;
    const int wid = tid >> 5;
    const int lid = tid & 31;
    const int m0  = blockIdx.x * MTILE;
    const int mhalf = wid & 1;          // which 16-token half
    const int khalf = wid >> 1;         // which 32-k half of each slab
    const int tp    = mhalf * 32 + lid; // thread index within khalf pair [0,64)
    const int barid = 1 + khalf;
    float* bias_sm = (float*)(smem + OFF_BIAS);

    if (tid < NE) bias_sm[tid] = bias[tid];

    float acch[8][4], accl[8][4];
#pragma unroll
    for (int j = 0; j < 8; j++)
#pragma unroll
        for (int i = 0; i < 4; i++) { acch[j][i] = 0.f; accl[j][i] = 0.f; }

    // A addressing: this lane owns rows (arow, arow+8) of its 16-token half
    const float* xr0 = x + (size_t)(m0 + mhalf * 16 + (lid >> 2)) * DK;
    const float* xr1 = xr0 + (size_t)8 * DK;
    const int kb_base = khalf * 32 + (lid & 3) * 2;

    // prologue: B slab 0 + A slab 0 regs
    issue_B_pair(sb, 0, 0, khalf, tp);
    float2 xc[2][4], xn[2][4];
#pragma unroll
    for (int s = 0; s < 2; s++) {
        int kb = kb_base + s * 16;
        xc[s][0] = *(const float2*)(xr0 + kb);
        xc[s][1] = *(const float2*)(xr1 + kb);
        xc[s][2] = *(const float2*)(xr0 + kb + 8);
        xc[s][3] = *(const float2*)(xr1 + kb + 8);
    }
    CP_WAIT0();
    BAR_PAIR(barid);

    const int lr = lid & 7;
    const int lg = lid >> 3;

#pragma unroll 1
    for (int c = 0; c < NSLAB; ++c) {
        const int p = c & 1, q = p ^ 1;
        const bool more = (c + 1 < NSLAB);
        if (more) {
            issue_B_pair(sb, q, c + 1, khalf, tp);
#pragma unroll
            for (int s = 0; s < 2; s++) {
                int kb = (c + 1) * KS + kb_base + s * 16;
                xn[s][0] = *(const float2*)(xr0 + kb);
                xn[s][1] = *(const float2*)(xr1 + kb);
                xn[s][2] = *(const float2*)(xr0 + kb + 8);
                xn[s][3] = *(const float2*)(xr1 + kb + 8);
            }
        }

        const uint32_t bufb = sb + p * BUF_BYTES;
#pragma unroll
        for (int s = 0; s < 2; s++) {
            // A fragments from registers (hi/lo split in-reg)
            uint32_t ah[4], al[4];
#pragma unroll
            for (int i = 0; i < 4; i++) ah[i] = packsplit(xc[s][i], al[i]);

            // B fragments from smem
            uint32_t bh[16], bl[16];
#pragma unroll
            for (int j2 = 0; j2 < 4; j2++) {
                uint32_t b_off = SWZ((uint32_t)((khalf * 32 + s * 16 + (lg & 1) * 8 + lr) * 128
                                                + (j2 * 16 + (lg >> 1) * 8) * 2));
                LDSM_X4T(bh[j2 * 4 + 0], bh[j2 * 4 + 1], bh[j2 * 4 + 2], bh[j2 * 4 + 3],
                         bufb + OFF_BH + b_off);
                LDSM_X4T(bl[j2 * 4 + 0], bl[j2 * 4 + 1], bl[j2 * 4 + 2], bl[j2 * 4 + 3],
                         bufb + OFF_BL + b_off);
            }
            // pass 1: acch += ah * bh
#pragma unroll
            for (int j = 0; j < 8; j++)
                MMA16816(acch[j], ah[0], ah[1], ah[2], ah[3],
                         bh[(j >> 1) * 4 + (j & 1) * 2], bh[(j >> 1) * 4 + (j & 1) * 2 + 1]);
            // pass 2: accl += ah * bl
#pragma unroll
            for (int j = 0; j < 8; j++)
                MMA16816(accl[j], ah[0], ah[1], ah[2], ah[3],
                         bl[(j >> 1) * 4 + (j & 1) * 2], bl[(j >> 1) * 4 + (j & 1) * 2 + 1]);
            // pass 3: accl += al * bh
#pragma unroll
            for (int j = 0; j < 8; j++)
                MMA16816(accl[j], al[0], al[1], al[2], al[3],
                         bh[(j >> 1) * 4 + (j & 1) * 2], bh[(j >> 1) * 4 + (j & 1) * 2 + 1]);
        }

        if (more) {
            CP_WAIT0();
            BAR_PAIR(barid);
#pragma unroll
            for (int s = 0; s < 2; s++)
#pragma unroll
                for (int i = 0; i < 4; i++) xc[s][i] = xn[s][i];
        }
    }

    // ---- epilogue: combine hi/lo, exchange K-halves via smem, softmax + top-2 ----
    __syncthreads();    // align pairs; smem reused for exchange
    const int qr = lid >> 2;
    const int qc = lid & 3;
    float L[2][16];
#pragma unroll
    for (int j = 0; j < 8; j++) {
        L[0][j * 2 + 0] = acch[j][0] + accl[j][0] * INV_LO;
        L[0][j * 2 + 1] = acch[j][1] + accl[j][1] * INV_LO;
        L[1][j * 2 + 0] = acch[j][2] + accl[j][2] * INV_LO;
        L[1][j * 2 + 1] = acch[j][3] + accl[j][3] * INV_LO;
    }

    float* ex = (float*)smem;          // [32 tokens][66] K-half exchange
    if (khalf == 1) {
#pragma unroll
        for (int t = 0; t < 2; t++) {
            int token = mhalf * 16 + t * 8 + qr;
#pragma unroll
            for (int j = 0; j < 8; j++) {
                int e = j * 8 + qc * 2;
                *(float2*)&ex[token * 66 + e] = make_float2(L[t][j * 2], L[t][j * 2 + 1]);
            }
        }
    }
    __syncthreads();

    if (khalf == 0) {
#pragma unroll
        for (int t = 0; t < 2; t++) {
            int token = mhalf * 16 + t * 8 + qr;
            float Lf[16];
#pragma unroll
            for (int j = 0; j < 8; j++) {
                int e = j * 8 + qc * 2;
                float2 o = *(const float2*)&ex[token * 66 + e];
                Lf[j * 2 + 0] = L[t][j * 2 + 0] + o.x + bias_sm[e];
                Lf[j * 2 + 1] = L[t][j * 2 + 1] + o.y + bias_sm[e + 1];
            }
            float v1 = -3.402823466e38f, v2 = -3.402823466e38f;
            int i1 = 0, i2 = 0;
#pragma unroll
            for (int u = 0; u < 16; u++) {
                int e = (u >> 1) * 8 + qc * 2 + (u & 1);
                float v = Lf[u];
                if (v > v1)      { v2 = v1; i2 = i1; v1 = v; i1 = e; }
                else if (v > v2) { v2 = v;  i2 = e; }
            }
#pragma unroll
            for (int d = 1; d <= 2; d <<= 1) {
                float w1 = __shfl_xor_sync(0xffffffffu, v1, d);
                int   j1 = __shfl_xor_sync(0xffffffffu, i1, d);
                float w2 = __shfl_xor_sync(0xffffffffu, v2, d);
                int   j2 = __shfl_xor_sync(0xffffffffu, i2, d);
                float c2v; int c2i;
                if (w1 > v1) { c2v = v1; c2i = i1; v1 = w1; i1 = j1; }
                else         { c2v = w1; c2i = j1; }
                if (c2v > v2) { v2 = c2v; i2 = c2i; }
                if (w2 > v2)  { v2 = w2;  i2 = j2; }
            }
            float s = 0.f;
#pragma unroll
            for (int u = 0; u < 16; u++) s += __expf(Lf[u] - v1);
#pragma unroll
            for (int d = 1; d <= 2; d <<= 1) s += __shfl_xor_sync(0xffffffffu, s, d);

            if (qc == 0) {
                int g = m0 + token;
                out[2 * g + 0] = (float)i1;
                out[2 * g + 1] = (float)i2;
                size_t voff = (size_t)2 * M;
                out[voff + 2 * g + 0] = 1.0f / s;
                out[voff + 2 * g + 1] = __expf(v2 - v1) / s;
            }
        }
    }
}

extern "C" void kernel_launch(void* const* d_in, const int* in_sizes, int n_in,
                              void* d_out, int out_size) {
    const float* x  = (const float*)d_in[0];
    const float* W  = (const float*)d_in[1];
    const float* b  = (const float*)d_in[2];
    float* out = (float*)d_out;

    int M = in_sizes[0] / DK;   // 16384
    wconv_kernel<<<(DK * NE / 4 + 255) / 256, 256>>>(W);
    cudaFuncSetAttribute(router_kernel,
                         cudaFuncAttributeMaxDynamicSharedMemorySize, SMEM_TOTAL);
    router_kernel<<<M / MTILE, NTHREADS, SMEM_TOTAL>>>(x, b, out, M);
}

// round 16
// speedup vs baseline: 1.0350x; 1.0350x over previous
#include <cuda_runtime.h>
#include <cuda_fp16.h>
#include <cstdint>

// TopKRouter via mma.sync f16 (hi/lo split, 3-pass): logits = x@W + b ; softmax E=64 ; top-2
// x: (16384, 2048) fp32, W: (2048, 64) fp32, b: (64,)
// out f32: [0..2M) = topk_idx as float (M,2) ; [2M..4M) = topk_vals (M,2)
// R16: warps = (mhalf x nhalf), full K per warp. A gmem->regs direct (no smem roundtrip),
//      acc regs halved (32), total regs <=128 -> 4 CTA/SM, grid 512 fully resident.

#define DK 2048
#define NE 64
#define KS 64
#define MTILE 32
#define NSLAB (DK / KS)         // 32
#define NTHREADS 128
#define SCALE_LO 2048.0f
#define INV_LO   4.8828125e-4f  // 2^-11

#define BUF_BYTES 16384         // Bh(8K) + Bl(8K) per stage
#define OFF_BH 0
#define OFF_BL 8192
#define OFF_BIAS (2 * BUF_BYTES)        // 32768
#define SMEM_TOTAL (OFF_BIAS + 512)

#define SWZ(a) ((a) ^ (((a) >> 3) & 0x70))

__device__ uint16_t g_Wh[DK * NE];
__device__ uint16_t g_Wl[DK * NE];

__device__ __forceinline__ uint32_t su32(const void* p) {
    uint32_t a;
    asm("{ .reg .u64 t; cvta.to.shared.u64 t, %1; cvt.u32.u64 %0, t; }" : "=r"(a) : "l"(p));
    return a;
}
__device__ __forceinline__ void cp_async16(uint32_t saddr, const void* g) {
    asm volatile("cp.async.cg.shared.global [%0], [%1], 16;" :: "r"(saddr), "l"(g));
}
#define CP_COMMIT() asm volatile("cp.async.commit_group;" ::: "memory")
#define CP_WAIT0()  asm volatile("cp.async.wait_group 0;" ::: "memory")

__device__ __forceinline__ void split_h(float v, uint16_t& h, uint16_t& l) {
    __half hh = __float2half_rn(v);
    float r = (v - __half2float(hh)) * SCALE_LO;
    __half ll = __float2half_rn(r);
    h = __half_as_ushort(hh);
    l = __half_as_ushort(ll);
}
__device__ __forceinline__ uint32_t packsplit(float2 v, uint32_t& lo) {
    uint16_t h0, l0, h1, l1;
    split_h(v.x, h0, l0);
    split_h(v.y, h1, l1);
    lo = (uint32_t)l0 | ((uint32_t)l1 << 16);
    return (uint32_t)h0 | ((uint32_t)h1 << 16);
}

#define LDSM_X4T(r0, r1, r2, r3, a)                                            \
    asm volatile("ldmatrix.sync.aligned.m8n8.x4.trans.shared.b16 {%0,%1,%2,%3}, [%4];" \
                 : "=r"(r0), "=r"(r1), "=r"(r2), "=r"(r3) : "r"(a))

#define MMA16816(d, a0, a1, a2, a3, b0, b1)                                    \
    asm volatile("mma.sync.aligned.m16n8k16.row.col.f32.f16.f16.f32 "          \
                 "{%0,%1,%2,%3}, {%4,%5,%6,%7}, {%8,%9}, {%0,%1,%2,%3};"       \
                 : "+f"((d)[0]), "+f"((d)[1]), "+f"((d)[2]), "+f"((d)[3])      \
                 : "r"(a0), "r"(a1), "r"(a2), "r"(a3), "r"(b0), "r"(b1))

__global__ void wconv_kernel(const float* __restrict__ W) {
    int i = (blockIdx.x * blockDim.x + threadIdx.x) * 4;
    float4 v = *(const float4*)(W + i);
    uint16_t h[4], l[4];
    split_h(v.x, h[0], l[0]); split_h(v.y, h[1], l[1]);
    split_h(v.z, h[2], l[2]); split_h(v.w, h[3], l[3]);
    *(uint2*)(g_Wh + i) = make_uint2((uint32_t)h[0] | ((uint32_t)h[1] << 16),
                                     (uint32_t)h[2] | ((uint32_t)h[3] << 16));
    *(uint2*)(g_Wl + i) = make_uint2((uint32_t)l[0] | ((uint32_t)l[1] << 16),
                                     (uint32_t)l[2] | ((uint32_t)l[3] << 16));
}

// Full 64-row B slab (hi+lo) into one stage buffer, 8 cp.async per thread.
__device__ __forceinline__ void issue_B(uint32_t sb, int buf, int c, int tid) {
    uint32_t dst = sb + buf * BUF_BYTES;
#pragma unroll
    for (int r = 0; r < 4; r++) {
        int lin = r * NTHREADS + tid;
        int k = lin >> 3, q = lin & 7;
        uint32_t off = SWZ((uint32_t)(k * 128 + q * 16));
        size_t ge = (size_t)(c * KS + k) * NE + q * 8;   // in halves
        cp_async16(dst + OFF_BH + off, (const char*)g_Wh + ge * 2);
        cp_async16(dst + OFF_BL + off, (const char*)g_Wl + ge * 2);
    }
    CP_COMMIT();
}

__global__ __launch_bounds__(NTHREADS, 4)
void router_kernel(const float* __restrict__ x,
                   const float* __restrict__ bias,
                   float* __restrict__ out,
                   int M)
{
    extern __shared__ char smem[];
    const uint32_t sb = su32(smem);
    const int tid = threadIdx.x;
    const int wid = tid >> 5;
    const int lid = tid & 31;
    const int m0  = blockIdx.x * MTILE;
    const int nhalf = wid & 1;          // which 32-expert half
    const int mhalf = wid >> 1;         // which 16-token half
    float* bias_sm = (float*)(smem + OFF_BIAS);

    if (tid < NE) bias_sm[tid] = bias[tid];

    // Accumulators: 4 n-tiles x 4 regs, hi + lo
    float acch[4][4], accl[4][4];
#pragma unroll
    for (int n = 0; n < 4; n++)
#pragma unroll
        for (int i = 0; i < 4; i++) { acch[n][i] = 0.f; accl[n][i] = 0.f; }

    const int qr = lid >> 2;
    const int qc = lid & 3;
    const float* xr0 = x + (size_t)(m0 + mhalf * 16 + qr) * DK;
    const float* xr1 = xr0 + (size_t)8 * DK;
    const int kb = qc * 2;

    // ---- prologue: B slab0 async; A slab0 -> regs -> packed hi/lo ----
    issue_B(sb, 0, 0, tid);
    float2 xn[4][4];
#pragma unroll
    for (int s = 0; s < 4; s++) {
        int k = s * 16 + kb;
        xn[s][0] = *(const float2*)(xr0 + k);
        xn[s][1] = *(const float2*)(xr1 + k);
        xn[s][2] = *(const float2*)(xr0 + k + 8);
        xn[s][3] = *(const float2*)(xr1 + k + 8);
    }
    uint32_t cah[4][4], cal[4][4];
#pragma unroll
    for (int s = 0; s < 4; s++)
#pragma unroll
        for (int i = 0; i < 4; i++) cah[s][i] = packsplit(xn[s][i], cal[s][i]);
    CP_WAIT0();
    __syncthreads();

    const int lr = lid & 7;
    const int lg = lid >> 3;

#pragma unroll 1
    for (int c = 0; c < NSLAB; ++c) {
        const int p = c & 1, q = p ^ 1;
        const bool more = (c + 1 < NSLAB);
        if (more) {
            issue_B(sb, q, c + 1, tid);
#pragma unroll
            for (int s = 0; s < 4; s++) {
                int k = (c + 1) * KS + s * 16 + kb;
                xn[s][0] = *(const float2*)(xr0 + k);
                xn[s][1] = *(const float2*)(xr1 + k);
                xn[s][2] = *(const float2*)(xr0 + k + 8);
                xn[s][3] = *(const float2*)(xr1 + k + 8);
            }
        }

        const uint32_t bufb = sb + p * BUF_BYTES;
#pragma unroll
        for (int s = 0; s < 4; s++) {
            // B fragments for this warp's 32 experts (2 j2 groups), hi + lo
            uint32_t bh[8], bl[8];
#pragma unroll
            for (int g = 0; g < 2; g++) {
                uint32_t b_off = SWZ((uint32_t)((s * 16 + (lg & 1) * 8 + lr) * 128
                                                + ((nhalf * 2 + g) * 16 + (lg >> 1) * 8) * 2));
                LDSM_X4T(bh[g * 4 + 0], bh[g * 4 + 1], bh[g * 4 + 2], bh[g * 4 + 3],
                         bufb + OFF_BH + b_off);
                LDSM_X4T(bl[g * 4 + 0], bl[g * 4 + 1], bl[g * 4 + 2], bl[g * 4 + 3],
                         bufb + OFF_BL + b_off);
            }
            // pass 1: acch += ah * bh
#pragma unroll
            for (int n = 0; n < 4; n++)
                MMA16816(acch[n], cah[s][0], cah[s][1], cah[s][2], cah[s][3],
                         bh[(n >> 1) * 4 + (n & 1) * 2], bh[(n >> 1) * 4 + (n & 1) * 2 + 1]);
            // pass 2: accl += ah * bl
#pragma unroll
            for (int n = 0; n < 4; n++)
                MMA16816(accl[n], cah[s][0], cah[s][1], cah[s][2], cah[s][3],
                         bl[(n >> 1) * 4 + (n & 1) * 2], bl[(n >> 1) * 4 + (n & 1) * 2 + 1]);
            // pass 3: accl += al * bh
#pragma unroll
            for (int n = 0; n < 4; n++)
                MMA16816(accl[n], cal[s][0], cal[s][1], cal[s][2], cal[s][3],
                         bh[(n >> 1) * 4 + (n & 1) * 2], bh[(n >> 1) * 4 + (n & 1) * 2 + 1]);
        }

        if (more) {
            CP_WAIT0();
            __syncthreads();
#pragma unroll
            for (int s = 0; s < 4; s++)
#pragma unroll
                for (int i = 0; i < 4; i++) cah[s][i] = packsplit(xn[s][i], cal[s][i]);
        }
    }

    // ---- epilogue: combine hi/lo, exchange expert halves, softmax + top-2 ----
    __syncthreads();    // all B reads done; smem reused for exchange
    float L[2][8];
#pragma unroll
    for (int n = 0; n < 4; n++) {
        L[0][n * 2 + 0] = acch[n][0] + accl[n][0] * INV_LO;
        L[0][n * 2 + 1] = acch[n][1] + accl[n][1] * INV_LO;
        L[1][n * 2 + 0] = acch[n][2] + accl[n][2] * INV_LO;
        L[1][n * 2 + 1] = acch[n][3] + accl[n][3] * INV_LO;
    }

    float* ex = (float*)smem;          // [32 tokens][66]: experts 32..63 partials
    if (nhalf == 1) {
#pragma unroll
        for (int t = 0; t < 2; t++) {
            int token = mhalf * 16 + t * 8 + qr;
#pragma unroll
            for (int n = 0; n < 4; n++)
                *(float2*)&ex[token * 66 + 32 + n * 8 + qc * 2] =
                    make_float2(L[t][n * 2], L[t][n * 2 + 1]);
        }
    }
    __syncthreads();

    if (nhalf == 0) {
#pragma unroll
        for (int t = 0; t < 2; t++) {
            int token = mhalf * 16 + t * 8 + qr;
            float Lf[16];
#pragma unroll
            for (int n = 0; n < 4; n++) {
                int el = n * 8 + qc * 2;
                Lf[n * 2 + 0] = L[t][n * 2 + 0] + bias_sm[el];
                Lf[n * 2 + 1] = L[t][n * 2 + 1] + bias_sm[el + 1];
                float2 o = *(const float2*)&ex[token * 66 + 32 + el];
                Lf[8 + n * 2 + 0] = o.x + bias_sm[32 + el];
                Lf[8 + n * 2 + 1] = o.y + bias_sm[32 + el + 1];
            }
            float v1 = -3.402823466e38f, v2 = -3.402823466e38f;
            int i1 = 0, i2 = 0;
#pragma unroll
            for (int u = 0; u < 16; u++) {
                int e = ((u >= 8) ? 32 : 0) + ((u & 7) >> 1) * 8 + qc * 2 + (u & 1);
                float v = Lf[u];
                if (v > v1)      { v2 = v1; i2 = i1; v1 = v; i1 = e; }
                else if (v > v2) { v2 = v;  i2 = e; }
            }
#pragma unroll
            for (int d = 1; d <= 2; d <<= 1) {
                float w1 = __shfl_xor_sync(0xffffffffu, v1, d);
                int   j1 = __shfl_xor_sync(0xffffffffu, i1, d);
                float w2 = __shfl_xor_sync(0xffffffffu, v2, d);
                int   j2 = __shfl_xor_sync(0xffffffffu, i2, d);
                float c2v; int c2i;
                if (w1 > v1) { c2v = v1; c2i = i1; v1 = w1; i1 = j1; }
                else         { c2v = w1; c2i = j1; }
                if (c2v > v2) { v2 = c2v; i2 = c2i; }
                if (w2 > v2)  { v2 = w2;  i2 = j2; }
            }
            float s = 0.f;
#pragma unroll
            for (int u = 0; u < 16; u++) s += __expf(Lf[u] - v1);
#pragma unroll
            for (int d = 1; d <= 2; d <<= 1) s += __shfl_xor_sync(0xffffffffu, s, d);

            if (qc == 0) {
                int g = m0 + token;
                out[2 * g + 0] = (float)i1;
                out[2 * g + 1] = (float)i2;
                size_t voff = (size_t)2 * M;
                out[voff + 2 * g + 0] = 1.0f / s;
                out[voff + 2 * g + 1] = __expf(v2 - v1) / s;
            }
        }
    }
}

extern "C" void kernel_launch(void* const* d_in, const int* in_sizes, int n_in,
                              void* d_out, int out_size) {
    const float* x  = (const float*)d_in[0];
    const float* W  = (const float*)d_in[1];
    const float* b  = (const float*)d_in[2];
    float* out = (float*)d_out;

    int M = in_sizes[0] / DK;   // 16384
    wconv_kernel<<<(DK * NE / 4 + 255) / 256, 256>>>(W);
    cudaFuncSetAttribute(router_kernel,
                         cudaFuncAttributeMaxDynamicSharedMemorySize, SMEM_TOTAL);
    router_kernel<<<M / MTILE, NTHREADS, SMEM_TOTAL>>>(x, b, out, M);
}